// round 10
// baseline (speedup 1.0000x reference)
#include <cuda_runtime.h>
#include <cuda_fp16.h>

// ---------------------------------------------------------------------------
// MeshUpConv via node-domain weight transform:
//   Z[n, k*32+o] = (X @ W[k])[n,o]  stored fp16; slot 9 = root -> acc (fp32).
//   edge: acc[dst, o] += sum_k B[e,k] * Z[src, k*32+o]   (fp32 accumulate)
// Edges counting-sorted by src once per launch -> EdgeRec array; the 3 edge
// kernels then get L1-resident Z gathers (avg degree 8).
// Node GEMM: 6 nodes/warp, f32x2 FMA, W in smem.
// edge_index arrives as int32 (JAX x64 disabled).
// ---------------------------------------------------------------------------

#define NMAX 50000
#define EMAX 400000

struct alignas(16) EdgeRec { int s, d; float t0, t1; };

__device__ __half g_Zh[NMAX * 288];   // 28.8 MB
__device__ float g_acc1[NMAX * 32];
__device__ float g_acc2[NMAX * 32];
__device__ int g_cnt[NMAX];
__device__ int g_pos[NMAX];
__device__ EdgeRec g_er[EMAX];

// ---- packed f32x2 helpers (sm_103a) ---------------------------------------
__device__ __forceinline__ unsigned long long pack2(float x) {
    unsigned long long r;
    asm("mov.b64 %0, {%1,%1};" : "=l"(r) : "f"(x));
    return r;
}
__device__ __forceinline__ void fma2(unsigned long long& d,
                                     unsigned long long a,
                                     unsigned long long b) {
    asm("fma.rn.f32x2 %0, %1, %2, %0;" : "+l"(d) : "l"(a), "l"(b));
}
__device__ __forceinline__ float2 unpack2(unsigned long long v) {
    float2 f;
    asm("mov.b64 {%0,%1}, %2;" : "=f"(f.x), "=f"(f.y) : "l"(v));
    return f;
}
__device__ __forceinline__ void red_add_v4(float* addr, float a, float b,
                                           float c, float d) {
    asm volatile("red.global.add.v4.f32 [%0], {%1,%2,%3,%4};"
                 :: "l"(addr), "f"(a), "f"(b), "f"(c), "f"(d)
                 : "memory");
}

// ---- counting sort by src --------------------------------------------------
__global__ void zero_cnt_kernel(int* cnt, int Nn) {
    int i = blockIdx.x * blockDim.x + threadIdx.x;
    if (i < Nn) cnt[i] = 0;
}

__global__ void hist_kernel(const int* __restrict__ ei, int* __restrict__ cnt,
                            int E) {
    int e = blockIdx.x * blockDim.x + threadIdx.x;
    if (e < E) atomicAdd(&cnt[ei[e]], 1);
}

// single-block exclusive scan: pos[i] = sum cnt[0..i-1]
__global__ void __launch_bounds__(1024) scan_kernel(
    const int* __restrict__ cnt, int* __restrict__ pos, int Nn) {
    __shared__ int ssum[1024];
    int tid = threadIdx.x;
    int chunk = (Nn + 1023) / 1024;
    int start = tid * chunk;
    int end = min(start + chunk, Nn);
    int s = 0;
    for (int i = start; i < end; i++) s += cnt[i];
    ssum[tid] = s;
    __syncthreads();
    for (int off = 1; off < 1024; off <<= 1) {
        int t = (tid >= off) ? ssum[tid - off] : 0;
        __syncthreads();
        ssum[tid] += t;
        __syncthreads();
    }
    int run = ssum[tid] - s;  // exclusive prefix of this chunk
    for (int i = start; i < end; i++) {
        pos[i] = run;
        run += cnt[i];
    }
}

__global__ void scatter_kernel(const int* __restrict__ ei,
                               const float* __restrict__ pseudo,
                               int* __restrict__ pos,
                               EdgeRec* __restrict__ er, int E) {
    int e = blockIdx.x * blockDim.x + threadIdx.x;
    if (e >= E) return;
    int s = ei[e];
    int d = ei[E + e];
    float2 ps = reinterpret_cast<const float2*>(pseudo)[e];
    int p = atomicAdd(&pos[s], 1);
    EdgeRec r;
    r.s = s; r.d = d; r.t0 = ps.x; r.t1 = ps.y;
    er[p] = r;  // STG.128
}

// ---- node GEMM, 6 nodes per warp -------------------------------------------
// MODE 0: X plain [N,CIN];  MODE 1: [relu(A)||S] (CIN=64);  MODE 2: relu(A) (CIN=32)
#define NT 6
template <int CIN, int MODE>
__global__ void __launch_bounds__(256, 2) node_gemm(
    const float* __restrict__ Xa, const float* __restrict__ Xb,
    const float* __restrict__ W, const float* __restrict__ root,
    const float* __restrict__ bias, __half* __restrict__ Zh,
    float* __restrict__ acc, int Nn, int nwarps) {
    extern __shared__ float Wsm[];  // [10][CIN][32]: 0-8 = W, 9 = root
    __shared__ float bsm[32];
    const int WT = 9 * CIN * 32;
    for (int i = threadIdx.x; i < WT; i += 256) Wsm[i] = W[i];
    for (int i = threadIdx.x; i < CIN * 32; i += 256) Wsm[WT + i] = root[i];
    if (threadIdx.x < 32) bsm[threadIdx.x] = bias[threadIdx.x];
    __syncthreads();

    const unsigned long long* Wsm2 =
        reinterpret_cast<const unsigned long long*>(Wsm);
    int lane = threadIdx.x & 31;
    int gw = (blockIdx.x * 256 + threadIdx.x) >> 5;

    for (int n0 = gw * NT; n0 < Nn; n0 += nwarps * NT) {
        float xlo[NT], xhi[NT];
#pragma unroll
        for (int j = 0; j < NT; j++) {
            int n = n0 + j;
            bool v = (n < Nn);
            if (MODE == 0) {
                xlo[j] = v ? Xa[(long long)n * CIN + lane] : 0.f;
                xhi[j] = (CIN == 64 && v) ? Xa[(long long)n * CIN + 32 + lane] : 0.f;
            } else if (MODE == 1) {
                xlo[j] = v ? fmaxf(Xa[n * 32 + lane], 0.f) : 0.f;
                xhi[j] = v ? Xb[n * 32 + lane] : 0.f;
            } else {
                xlo[j] = v ? fmaxf(Xa[n * 32 + lane], 0.f) : 0.f;
                xhi[j] = 0.f;
            }
        }

        unsigned long long au[NT][5];
#pragma unroll
        for (int j = 0; j < NT; j++)
#pragma unroll
            for (int i = 0; i < 5; i++) au[j][i] = 0ULL;

#pragma unroll
        for (int c = 0; c < CIN; c++) {
            unsigned long long w[5];
#pragma unroll
            for (int i = 0; i < 5; i++) {
                int P = lane + 32 * i;  // pair id 0..159
                w[i] = Wsm2[(P >> 4) * (CIN * 16) + c * 16 + (P & 15)];
            }
#pragma unroll
            for (int j = 0; j < NT; j++) {
                float xc =
                    __shfl_sync(0xffffffffu, (c < 32) ? xlo[j] : xhi[j], c & 31);
                unsigned long long xp = pack2(xc);
#pragma unroll
                for (int i = 0; i < 5; i++) fma2(au[j][i], w[i], xp);
            }
        }

#pragma unroll
        for (int j = 0; j < NT; j++) {
            int n = n0 + j;
            if (n >= Nn) break;
#pragma unroll
            for (int i = 0; i < 5; i++) {
                int P = lane + 32 * i;
                int slot = P >> 4, pr = P & 15;
                float2 f = unpack2(au[j][i]);
                if (slot < 9) {
                    *reinterpret_cast<__half2*>(&Zh[(long long)n * 288 + 2 * P]) =
                        __floats2half2_rn(f.x, f.y);
                } else {
                    acc[n * 32 + 2 * pr + 0] = f.x + bsm[2 * pr + 0];
                    acc[n * 32 + 2 * pr + 1] = f.y + bsm[2 * pr + 1];
                }
            }
        }
    }
}

// ---- edge phase: 8 lanes/edge, 4 fp16 channels/lane, src-sorted records ----
__global__ void __launch_bounds__(256) edge_kernel(
    const __half* __restrict__ Zh, const EdgeRec* __restrict__ er,
    float* __restrict__ acc, int E) {
    int warp = (blockIdx.x * 256 + threadIdx.x) >> 5;
    int lane = threadIdx.x & 31;
    int sub = lane >> 3;   // edge within warp (0..3)
    int li = lane & 7;     // half4-channel group (0..7)
    int idx = warp * 4 + sub;
    if (idx >= E) return;

    uint4 rv = __ldg(reinterpret_cast<const uint4*>(er) + idx);
    int s = (int)rv.x;
    int d = (int)rv.y;
    float t0 = __uint_as_float(rv.z);
    float t1 = __uint_as_float(rv.w);

    float q0[3], q1[3];
    q0[0] = 0.5f * (1.f - t0) * (1.f - t0);
    q0[1] = -t0 * t0 + t0 + 0.5f;
    q0[2] = 0.5f * t0 * t0;
    q1[0] = 0.5f * (1.f - t1) * (1.f - t1);
    q1[1] = -t1 * t1 + t1 + 0.5f;
    q1[2] = 0.5f * t1 * t1;

    // lane reads 4 halves (8B) per slot at half-offset k*32 + li*4
    const uint2* zs =
        reinterpret_cast<const uint2*>(Zh + (long long)s * 288) + li;
    float ax = 0.f, ay = 0.f, az = 0.f, aw = 0.f;
#pragma unroll
    for (int k1 = 0; k1 < 3; k1++) {
#pragma unroll
        for (int k0 = 0; k0 < 3; k0++) {
            float bk = q1[k1] * q0[k0];
            uint2 z = __ldg(zs + (k1 * 3 + k0) * 8);
            float2 f0 = __half22float2(*reinterpret_cast<__half2*>(&z.x));
            float2 f1 = __half22float2(*reinterpret_cast<__half2*>(&z.y));
            ax = fmaf(bk, f0.x, ax);
            ay = fmaf(bk, f0.y, ay);
            az = fmaf(bk, f1.x, az);
            aw = fmaf(bk, f1.y, aw);
        }
    }

    red_add_v4(acc + (long long)d * 32 + li * 4, ax, ay, az, aw);
}

__global__ void relu4_kernel(float4* __restrict__ a, int total4) {
    int i = blockIdx.x * blockDim.x + threadIdx.x;
    if (i < total4) {
        float4 v = a[i];
        v.x = fmaxf(v.x, 0.f); v.y = fmaxf(v.y, 0.f);
        v.z = fmaxf(v.z, 0.f); v.w = fmaxf(v.w, 0.f);
        a[i] = v;
    }
}

// ---------------------------------------------------------------------------
extern "C" void kernel_launch(void* const* d_in, const int* in_sizes, int n_in,
                              void* d_out, int out_size) {
    const float* x = (const float*)d_in[0];      // [N,64]
    const int* ei = (const int*)d_in[1];         // [2,E] int32
    const float* pseudo = (const float*)d_in[2]; // [E,2]
    const float* skip = (const float*)d_in[3];   // [N,32]
    const float* W1 = (const float*)d_in[4];     // [9,64,32]
    const float* root1 = (const float*)d_in[5];  // [64,32]
    const float* b1 = (const float*)d_in[6];     // [32]
    const float* W2 = (const float*)d_in[7];     // [9,32,32]
    const float* root2 = (const float*)d_in[8];  // [32,32]
    const float* b2 = (const float*)d_in[9];     // [32]

    int Nn = in_sizes[0] / 64;
    int E = in_sizes[1] / 2;

    __half* Zh;
    float *acc1, *acc2;
    int *cnt, *pos;
    EdgeRec* er;
    cudaGetSymbolAddress((void**)&Zh, g_Zh);
    cudaGetSymbolAddress((void**)&acc1, g_acc1);
    cudaGetSymbolAddress((void**)&acc2, g_acc2);
    cudaGetSymbolAddress((void**)&cnt, g_cnt);
    cudaGetSymbolAddress((void**)&pos, g_pos);
    cudaGetSymbolAddress((void**)&er, g_er);

    const int SM64 = 10 * 64 * 32 * 4;  // 81920 B
    const int SM32 = 10 * 32 * 32 * 4;  // 40960 B
    cudaFuncSetAttribute(node_gemm<64, 0>,
                         cudaFuncAttributeMaxDynamicSharedMemorySize, SM64);
    cudaFuncSetAttribute(node_gemm<64, 1>,
                         cudaFuncAttributeMaxDynamicSharedMemorySize, SM64);
    cudaFuncSetAttribute(node_gemm<32, 2>,
                         cudaFuncAttributeMaxDynamicSharedMemorySize, SM32);

    const int G = 296;       // 2 blocks/SM
    int eb = (E + 31) / 32;  // 4 edges/warp, 8 warps/block
    int nb4 = (Nn * 32 / 4 + 255) / 256;
    int ebs = (E + 255) / 256;
    int nbn = (Nn + 255) / 256;
    float* out = (float*)d_out;

    // ---- counting sort of edges by src (amortized over 3 edge passes)
    zero_cnt_kernel<<<nbn, 256>>>(cnt, Nn);
    hist_kernel<<<ebs, 256>>>(ei, cnt, E);
    scan_kernel<<<1, 1024>>>(cnt, pos, Nn);
    scatter_kernel<<<ebs, 256>>>(ei, pseudo, pos, er, E);

    // ---- layer 1: x -> Zh, acc1(root) ; edge -> acc1
    node_gemm<64, 0><<<G, 256, SM64>>>(x, nullptr, W1, root1, b1, Zh, acc1,
                                       Nn, G * 8);
    edge_kernel<<<eb, 256>>>(Zh, er, acc1, E);

    // ---- layer 2: [relu(acc1)||skip] -> Zh, acc2(root) ; edge -> acc2
    node_gemm<64, 1><<<G, 256, SM64>>>(acc1, skip, W1, root1, b1, Zh, acc2,
                                       Nn, G * 8);
    edge_kernel<<<eb, 256>>>(Zh, er, acc2, E);

    // ---- layer 3: relu(acc2) -> Zh, out(root) ; edge -> out ; relu
    node_gemm<32, 2><<<G, 256, SM32>>>(acc2, nullptr, W2, root2, b2, Zh, out,
                                       Nn, G * 8);
    edge_kernel<<<eb, 256>>>(Zh, er, out, E);
    relu4_kernel<<<nb4, 256>>>((float4*)out, Nn * 32 / 4);
}

// round 11
// speedup vs baseline: 1.3043x; 1.3043x over previous
#include <cuda_runtime.h>
#include <cuda_fp16.h>

// ---------------------------------------------------------------------------
// MeshUpConv via node-domain weight transform:
//   Z[n, k*32+o] = (X @ W[k])[n,o]  stored fp16; slot 9 = root -> acc (fp32).
//   edge: acc[dst, o] += sum_k B[e,k] * Z[src, k*32+o]   (fp32 accumulate)
// Node GEMM: 6 nodes/warp (no spill), f32x2 FMA, W in smem.
// Edge: 8 lanes/edge, uint2 fp16 loads (best measured shape), vector REDG.
// No edge sorting (measured cost-neutral on gather, +40us overhead).
// edge_index arrives as int32 (JAX x64 disabled).
// ---------------------------------------------------------------------------

#define NMAX 50000
#define EMAX 400000

__device__ __half g_Zh[NMAX * 288];   // 28.8 MB
__device__ float g_acc1[NMAX * 32];
__device__ float g_acc2[NMAX * 32];

// ---- packed f32x2 helpers (sm_103a) ---------------------------------------
__device__ __forceinline__ unsigned long long pack2(float x) {
    unsigned long long r;
    asm("mov.b64 %0, {%1,%1};" : "=l"(r) : "f"(x));
    return r;
}
__device__ __forceinline__ void fma2(unsigned long long& d,
                                     unsigned long long a,
                                     unsigned long long b) {
    asm("fma.rn.f32x2 %0, %1, %2, %0;" : "+l"(d) : "l"(a), "l"(b));
}
__device__ __forceinline__ float2 unpack2(unsigned long long v) {
    float2 f;
    asm("mov.b64 {%0,%1}, %2;" : "=f"(f.x), "=f"(f.y) : "l"(v));
    return f;
}
__device__ __forceinline__ void red_add_v4(float* addr, float a, float b,
                                           float c, float d) {
    asm volatile("red.global.add.v4.f32 [%0], {%1,%2,%3,%4};"
                 :: "l"(addr), "f"(a), "f"(b), "f"(c), "f"(d)
                 : "memory");
}

// ---- node GEMM, 6 nodes per warp (NT=6, no spill) --------------------------
// MODE 0: X plain [N,CIN];  MODE 1: [relu(A)||S] (CIN=64);  MODE 2: relu(A) (CIN=32)
#define NT 6
template <int CIN, int MODE>
__global__ void __launch_bounds__(256, 2) node_gemm(
    const float* __restrict__ Xa, const float* __restrict__ Xb,
    const float* __restrict__ W, const float* __restrict__ root,
    const float* __restrict__ bias, __half* __restrict__ Zh,
    float* __restrict__ acc, int Nn, int nwarps) {
    extern __shared__ float Wsm[];  // [10][CIN][32]: 0-8 = W, 9 = root
    __shared__ float bsm[32];
    const int WT = 9 * CIN * 32;
    for (int i = threadIdx.x; i < WT; i += 256) Wsm[i] = W[i];
    for (int i = threadIdx.x; i < CIN * 32; i += 256) Wsm[WT + i] = root[i];
    if (threadIdx.x < 32) bsm[threadIdx.x] = bias[threadIdx.x];
    __syncthreads();

    const unsigned long long* Wsm2 =
        reinterpret_cast<const unsigned long long*>(Wsm);
    int lane = threadIdx.x & 31;
    int gw = (blockIdx.x * 256 + threadIdx.x) >> 5;

    for (int n0 = gw * NT; n0 < Nn; n0 += nwarps * NT) {
        float xlo[NT], xhi[NT];
#pragma unroll
        for (int j = 0; j < NT; j++) {
            int n = n0 + j;
            bool v = (n < Nn);
            if (MODE == 0) {
                xlo[j] = v ? Xa[(long long)n * CIN + lane] : 0.f;
                xhi[j] = (CIN == 64 && v) ? Xa[(long long)n * CIN + 32 + lane] : 0.f;
            } else if (MODE == 1) {
                xlo[j] = v ? fmaxf(Xa[n * 32 + lane], 0.f) : 0.f;
                xhi[j] = v ? Xb[n * 32 + lane] : 0.f;
            } else {
                xlo[j] = v ? fmaxf(Xa[n * 32 + lane], 0.f) : 0.f;
                xhi[j] = 0.f;
            }
        }

        unsigned long long au[NT][5];
#pragma unroll
        for (int j = 0; j < NT; j++)
#pragma unroll
            for (int i = 0; i < 5; i++) au[j][i] = 0ULL;

#pragma unroll
        for (int c = 0; c < CIN; c++) {
            unsigned long long w[5];
#pragma unroll
            for (int i = 0; i < 5; i++) {
                int P = lane + 32 * i;  // pair id 0..159
                w[i] = Wsm2[(P >> 4) * (CIN * 16) + c * 16 + (P & 15)];
            }
#pragma unroll
            for (int j = 0; j < NT; j++) {
                float xc =
                    __shfl_sync(0xffffffffu, (c < 32) ? xlo[j] : xhi[j], c & 31);
                unsigned long long xp = pack2(xc);
#pragma unroll
                for (int i = 0; i < 5; i++) fma2(au[j][i], w[i], xp);
            }
        }

#pragma unroll
        for (int j = 0; j < NT; j++) {
            int n = n0 + j;
            if (n >= Nn) break;
#pragma unroll
            for (int i = 0; i < 5; i++) {
                int P = lane + 32 * i;
                int slot = P >> 4, pr = P & 15;
                float2 f = unpack2(au[j][i]);
                if (slot < 9) {
                    *reinterpret_cast<__half2*>(&Zh[(long long)n * 288 + 2 * P]) =
                        __floats2half2_rn(f.x, f.y);
                } else {
                    acc[n * 32 + 2 * pr + 0] = f.x + bsm[2 * pr + 0];
                    acc[n * 32 + 2 * pr + 1] = f.y + bsm[2 * pr + 1];
                }
            }
        }
    }
}

// ---- edge phase: 8 lanes/edge, 4 fp16 channels per lane, fp32 accumulate ---
__global__ void __launch_bounds__(256) edge_kernel(
    const __half* __restrict__ Zh, const int* __restrict__ ei,
    const float* __restrict__ pseudo, float* __restrict__ acc, int E) {
    int warp = (blockIdx.x * 256 + threadIdx.x) >> 5;
    int lane = threadIdx.x & 31;
    int sub = lane >> 3;   // edge within warp (0..3)
    int li = lane & 7;     // half4-channel group (0..7)
    int e = warp * 4 + sub;
    if (e >= E) return;

    int s = __ldg(ei + e);
    int d = __ldg(ei + E + e);
    float2 ps = __ldg(reinterpret_cast<const float2*>(pseudo) + e);
    float t0 = ps.x, t1 = ps.y;

    float q0[3], q1[3];
    q0[0] = 0.5f * (1.f - t0) * (1.f - t0);
    q0[1] = -t0 * t0 + t0 + 0.5f;
    q0[2] = 0.5f * t0 * t0;
    q1[0] = 0.5f * (1.f - t1) * (1.f - t1);
    q1[1] = -t1 * t1 + t1 + 0.5f;
    q1[2] = 0.5f * t1 * t1;

    // lane reads 4 halves (8B) per slot at half-offset k*32 + li*4
    const uint2* zs =
        reinterpret_cast<const uint2*>(Zh + (long long)s * 288) + li;
    float ax = 0.f, ay = 0.f, az = 0.f, aw = 0.f;
#pragma unroll
    for (int k1 = 0; k1 < 3; k1++) {
#pragma unroll
        for (int k0 = 0; k0 < 3; k0++) {
            float bk = q1[k1] * q0[k0];
            uint2 z = __ldg(zs + (k1 * 3 + k0) * 8);
            float2 f0 = __half22float2(*reinterpret_cast<__half2*>(&z.x));
            float2 f1 = __half22float2(*reinterpret_cast<__half2*>(&z.y));
            ax = fmaf(bk, f0.x, ax);
            ay = fmaf(bk, f0.y, ay);
            az = fmaf(bk, f1.x, az);
            aw = fmaf(bk, f1.y, aw);
        }
    }

    red_add_v4(acc + (long long)d * 32 + li * 4, ax, ay, az, aw);
}

__global__ void relu4_kernel(float4* __restrict__ a, int total4) {
    int i = blockIdx.x * blockDim.x + threadIdx.x;
    if (i < total4) {
        float4 v = a[i];
        v.x = fmaxf(v.x, 0.f); v.y = fmaxf(v.y, 0.f);
        v.z = fmaxf(v.z, 0.f); v.w = fmaxf(v.w, 0.f);
        a[i] = v;
    }
}

// ---------------------------------------------------------------------------
extern "C" void kernel_launch(void* const* d_in, const int* in_sizes, int n_in,
                              void* d_out, int out_size) {
    const float* x = (const float*)d_in[0];      // [N,64]
    const int* ei = (const int*)d_in[1];         // [2,E] int32
    const float* pseudo = (const float*)d_in[2]; // [E,2]
    const float* skip = (const float*)d_in[3];   // [N,32]
    const float* W1 = (const float*)d_in[4];     // [9,64,32]
    const float* root1 = (const float*)d_in[5];  // [64,32]
    const float* b1 = (const float*)d_in[6];     // [32]
    const float* W2 = (const float*)d_in[7];     // [9,32,32]
    const float* root2 = (const float*)d_in[8];  // [32,32]
    const float* b2 = (const float*)d_in[9];     // [32]

    int Nn = in_sizes[0] / 64;
    int E = in_sizes[1] / 2;

    __half* Zh;
    float *acc1, *acc2;
    cudaGetSymbolAddress((void**)&Zh, g_Zh);
    cudaGetSymbolAddress((void**)&acc1, g_acc1);
    cudaGetSymbolAddress((void**)&acc2, g_acc2);

    const int SM64 = 10 * 64 * 32 * 4;  // 81920 B
    const int SM32 = 10 * 32 * 32 * 4;  // 40960 B
    cudaFuncSetAttribute(node_gemm<64, 0>,
                         cudaFuncAttributeMaxDynamicSharedMemorySize, SM64);
    cudaFuncSetAttribute(node_gemm<64, 1>,
                         cudaFuncAttributeMaxDynamicSharedMemorySize, SM64);
    cudaFuncSetAttribute(node_gemm<32, 2>,
                         cudaFuncAttributeMaxDynamicSharedMemorySize, SM32);

    const int G = 296;       // 2 blocks/SM
    int eb = (E + 31) / 32;  // 4 edges/warp, 8 warps/block
    int nb4 = (Nn * 32 / 4 + 255) / 256;
    float* out = (float*)d_out;

    // ---- layer 1: x -> Zh, acc1(root) ; edge -> acc1
    node_gemm<64, 0><<<G, 256, SM64>>>(x, nullptr, W1, root1, b1, Zh, acc1,
                                       Nn, G * 8);
    edge_kernel<<<eb, 256>>>(Zh, ei, pseudo, acc1, E);

    // ---- layer 2: [relu(acc1)||skip] -> Zh, acc2(root) ; edge -> acc2
    node_gemm<64, 1><<<G, 256, SM64>>>(acc1, skip, W1, root1, b1, Zh, acc2,
                                       Nn, G * 8);
    edge_kernel<<<eb, 256>>>(Zh, ei, pseudo, acc2, E);

    // ---- layer 3: relu(acc2) -> Zh, out(root) ; edge -> out ; relu
    node_gemm<32, 2><<<G, 256, SM32>>>(acc2, nullptr, W2, root2, b2, Zh, out,
                                       Nn, G * 8);
    edge_kernel<<<eb, 256>>>(Zh, ei, pseudo, out, E);
    relu4_kernel<<<nb4, 256>>>((float4*)out, Nn * 32 / 4);
}

// round 13
// speedup vs baseline: 1.8594x; 1.4256x over previous
#include <cuda_runtime.h>
#include <cuda_fp16.h>

// ---------------------------------------------------------------------------
// MeshUpConv via node-domain weight transform, tensor-core node GEMM:
//   Z[n, k*32+o] = (X @ W[k])[n,o]  (HMMA m16n8k16, fp16 in / fp32 accum,
//   Z stored fp16); slot 9 = root -> acc (+bias, fp32).
//   edge: acc[dst, o] += sum_k B[e,k] * Z[src, k*32+o]   (fp32 accumulate)
// Edge: 8 lanes/edge, uint2 fp16 loads, vector REDG (best measured shape).
// edge_index arrives as int32 (JAX x64 disabled).
// ---------------------------------------------------------------------------

#define NMAX 50000
#define EMAX 400000

__device__ __half g_Zh[NMAX * 288];   // 28.8 MB
__device__ float g_acc1[NMAX * 32];
__device__ float g_acc2[NMAX * 32];

__device__ __forceinline__ void red_add_v4(float* addr, float a, float b,
                                           float c, float d) {
    asm volatile("red.global.add.v4.f32 [%0], {%1,%2,%3,%4};"
                 :: "l"(addr), "f"(a), "f"(b), "f"(c), "f"(d)
                 : "memory");
}

__device__ __forceinline__ unsigned h2u(float a, float b) {
    __half2 h = __floats2half2_rn(a, b);
    return *reinterpret_cast<unsigned*>(&h);
}

__device__ __forceinline__ void mma16816(float& c0, float& c1, float& c2,
                                         float& c3, unsigned a0, unsigned a1,
                                         unsigned a2, unsigned a3, unsigned b0,
                                         unsigned b1) {
    asm volatile(
        "mma.sync.aligned.m16n8k16.row.col.f32.f16.f16.f32 "
        "{%0,%1,%2,%3}, {%4,%5,%6,%7}, {%8,%9}, {%0,%1,%2,%3};"
        : "+f"(c0), "+f"(c1), "+f"(c2), "+f"(c3)
        : "r"(a0), "r"(a1), "r"(a2), "r"(a3), "r"(b0), "r"(b1));
}

// ---- HMMA node GEMM: one m16-node tile per warp, 40 n8-tiles (320 cols) ----
// KT = k16 chunks (4 for CIN=64, 2 for CIN=32).
// MODE 0: X plain; MODE 1: [relu(A)||S]; MODE 2: relu(A).
template <int KT, int MODE>
__global__ void __launch_bounds__(256) node_hmma(
    const float* __restrict__ Xa, const float* __restrict__ Xb,
    const float* __restrict__ W, const float* __restrict__ root,
    const float* __restrict__ bias, __half* __restrict__ Zh,
    float* __restrict__ acc, int Nn) {
    extern __shared__ unsigned long long Bfrag[];  // [KT][40][32] (b0|b1<<32)
    __shared__ float bsm[32];
    const int CIN = KT * 16;

    // Build B fragments in the exact mma lane layout (col-major k16 x n8):
    // b0 = {B[t*2][n], B[t*2+1][n]}, b1 = {B[t*2+8][n], B[t*2+9][n]},
    // n = nt*8 + g, g = lane>>2, t = lane&3, B[k][slot*32+o] = W[slot][k][o].
    for (int i = threadIdx.x; i < KT * 40 * 32; i += 256) {
        int lane = i & 31;
        int nt = (i >> 5) % 40;
        int kt = i / (40 * 32);
        int g = lane >> 2, t = lane & 3;
        int n = nt * 8 + g;
        int slot = n >> 5, o = n & 31;
        int kbase = kt * 16 + t * 2;
        const float* src = (slot < 9) ? (W + slot * CIN * 32) : root;
        float w0 = src[(kbase + 0) * 32 + o];
        float w1 = src[(kbase + 1) * 32 + o];
        float w8 = src[(kbase + 8) * 32 + o];
        float w9 = src[(kbase + 9) * 32 + o];
        Bfrag[i] = (unsigned long long)h2u(w0, w1) |
                   ((unsigned long long)h2u(w8, w9) << 32);
    }
    if (threadIdx.x < 32) bsm[threadIdx.x] = bias[threadIdx.x];
    __syncthreads();

    int w = blockIdx.x * 8 + (threadIdx.x >> 5);
    int lane = threadIdx.x & 31;
    int n0 = w * 16;
    if (n0 >= Nn) return;
    int g = lane >> 2, t = lane & 3;
    int r1 = n0 + g, r2 = n0 + g + 8;
    int r1c = min(r1, Nn - 1), r2c = min(r2, Nn - 1);
    bool v1 = (r1 < Nn), v2 = (r2 < Nn);

    // A fragments: a0={A[g][t*2..]}, a1={A[g+8][..]}, a2/a3 = cols +8.
    unsigned a[KT][4];
    if (MODE == 0) {
        const float2* x1 = reinterpret_cast<const float2*>(Xa + (long long)r1c * CIN);
        const float2* x2 = reinterpret_cast<const float2*>(Xa + (long long)r2c * CIN);
#pragma unroll
        for (int kc = 0; kc < KT; kc++) {
            float2 p;
            p = __ldg(x1 + kc * 8 + t);     a[kc][0] = h2u(p.x, p.y);
            p = __ldg(x2 + kc * 8 + t);     a[kc][1] = h2u(p.x, p.y);
            p = __ldg(x1 + kc * 8 + t + 4); a[kc][2] = h2u(p.x, p.y);
            p = __ldg(x2 + kc * 8 + t + 4); a[kc][3] = h2u(p.x, p.y);
        }
    } else if (MODE == 1) {
        const float2* x1 = reinterpret_cast<const float2*>(Xa + (long long)r1c * 32);
        const float2* x2 = reinterpret_cast<const float2*>(Xa + (long long)r2c * 32);
        const float2* s1 = reinterpret_cast<const float2*>(Xb + (long long)r1c * 32);
        const float2* s2 = reinterpret_cast<const float2*>(Xb + (long long)r2c * 32);
#pragma unroll
        for (int kc = 0; kc < 2; kc++) {
            float2 p;
            p = __ldg(x1 + kc * 8 + t);
            a[kc][0] = h2u(fmaxf(p.x, 0.f), fmaxf(p.y, 0.f));
            p = __ldg(x2 + kc * 8 + t);
            a[kc][1] = h2u(fmaxf(p.x, 0.f), fmaxf(p.y, 0.f));
            p = __ldg(x1 + kc * 8 + t + 4);
            a[kc][2] = h2u(fmaxf(p.x, 0.f), fmaxf(p.y, 0.f));
            p = __ldg(x2 + kc * 8 + t + 4);
            a[kc][3] = h2u(fmaxf(p.x, 0.f), fmaxf(p.y, 0.f));
            p = __ldg(s1 + kc * 8 + t);     a[kc + 2][0] = h2u(p.x, p.y);
            p = __ldg(s2 + kc * 8 + t);     a[kc + 2][1] = h2u(p.x, p.y);
            p = __ldg(s1 + kc * 8 + t + 4); a[kc + 2][2] = h2u(p.x, p.y);
            p = __ldg(s2 + kc * 8 + t + 4); a[kc + 2][3] = h2u(p.x, p.y);
        }
    } else {
        const float2* x1 = reinterpret_cast<const float2*>(Xa + (long long)r1c * 32);
        const float2* x2 = reinterpret_cast<const float2*>(Xa + (long long)r2c * 32);
#pragma unroll
        for (int kc = 0; kc < KT; kc++) {
            float2 p;
            p = __ldg(x1 + kc * 8 + t);
            a[kc][0] = h2u(fmaxf(p.x, 0.f), fmaxf(p.y, 0.f));
            p = __ldg(x2 + kc * 8 + t);
            a[kc][1] = h2u(fmaxf(p.x, 0.f), fmaxf(p.y, 0.f));
            p = __ldg(x1 + kc * 8 + t + 4);
            a[kc][2] = h2u(fmaxf(p.x, 0.f), fmaxf(p.y, 0.f));
            p = __ldg(x2 + kc * 8 + t + 4);
            a[kc][3] = h2u(fmaxf(p.x, 0.f), fmaxf(p.y, 0.f));
        }
    }

#pragma unroll
    for (int nt = 0; nt < 40; nt++) {
        float c0 = 0.f, c1 = 0.f, c2 = 0.f, c3 = 0.f;
#pragma unroll
        for (int kt = 0; kt < KT; kt++) {
            unsigned long long bb = Bfrag[(kt * 40 + nt) * 32 + lane];
            mma16816(c0, c1, c2, c3, a[kt][0], a[kt][1], a[kt][2], a[kt][3],
                     (unsigned)bb, (unsigned)(bb >> 32));
        }
        if (nt < 36) {  // slots 0-8 -> Zh fp16
            int col = (nt >> 2) * 32 + (nt & 3) * 8 + t * 2;
            if (v1)
                *reinterpret_cast<__half2*>(&Zh[(long long)r1 * 288 + col]) =
                    __floats2half2_rn(c0, c1);
            if (v2)
                *reinterpret_cast<__half2*>(&Zh[(long long)r2 * 288 + col]) =
                    __floats2half2_rn(c2, c3);
        } else {  // slot 9 = root -> acc fp32 + bias
            int col = (nt - 36) * 8 + t * 2;
            if (v1) {
                float2 f = make_float2(c0 + bsm[col], c1 + bsm[col + 1]);
                *reinterpret_cast<float2*>(&acc[(long long)r1 * 32 + col]) = f;
            }
            if (v2) {
                float2 f = make_float2(c2 + bsm[col], c3 + bsm[col + 1]);
                *reinterpret_cast<float2*>(&acc[(long long)r2 * 32 + col]) = f;
            }
        }
    }
}

// ---- edge phase: 8 lanes/edge, 4 fp16 channels per lane, fp32 accumulate ---
__global__ void __launch_bounds__(256) edge_kernel(
    const __half* __restrict__ Zh, const int* __restrict__ ei,
    const float* __restrict__ pseudo, float* __restrict__ acc, int E) {
    int warp = (blockIdx.x * 256 + threadIdx.x) >> 5;
    int lane = threadIdx.x & 31;
    int sub = lane >> 3;   // edge within warp (0..3)
    int li = lane & 7;     // half4-channel group (0..7)
    int e = warp * 4 + sub;
    if (e >= E) return;

    int s = __ldg(ei + e);
    int d = __ldg(ei + E + e);
    float2 ps = __ldg(reinterpret_cast<const float2*>(pseudo) + e);
    float t0 = ps.x, t1 = ps.y;

    float q0[3], q1[3];
    q0[0] = 0.5f * (1.f - t0) * (1.f - t0);
    q0[1] = -t0 * t0 + t0 + 0.5f;
    q0[2] = 0.5f * t0 * t0;
    q1[0] = 0.5f * (1.f - t1) * (1.f - t1);
    q1[1] = -t1 * t1 + t1 + 0.5f;
    q1[2] = 0.5f * t1 * t1;

    const uint2* zs =
        reinterpret_cast<const uint2*>(Zh + (long long)s * 288) + li;
    float ax = 0.f, ay = 0.f, az = 0.f, aw = 0.f;
#pragma unroll
    for (int k1 = 0; k1 < 3; k1++) {
#pragma unroll
        for (int k0 = 0; k0 < 3; k0++) {
            float bk = q1[k1] * q0[k0];
            uint2 z = __ldg(zs + (k1 * 3 + k0) * 8);
            float2 f0 = __half22float2(*reinterpret_cast<__half2*>(&z.x));
            float2 f1 = __half22float2(*reinterpret_cast<__half2*>(&z.y));
            ax = fmaf(bk, f0.x, ax);
            ay = fmaf(bk, f0.y, ay);
            az = fmaf(bk, f1.x, az);
            aw = fmaf(bk, f1.y, aw);
        }
    }

    red_add_v4(acc + (long long)d * 32 + li * 4, ax, ay, az, aw);
}

__global__ void relu4_kernel(float4* __restrict__ a, int total4) {
    int i = blockIdx.x * blockDim.x + threadIdx.x;
    if (i < total4) {
        float4 v = a[i];
        v.x = fmaxf(v.x, 0.f); v.y = fmaxf(v.y, 0.f);
        v.z = fmaxf(v.z, 0.f); v.w = fmaxf(v.w, 0.f);
        a[i] = v;
    }
}

// ---------------------------------------------------------------------------
extern "C" void kernel_launch(void* const* d_in, const int* in_sizes, int n_in,
                              void* d_out, int out_size) {
    const float* x = (const float*)d_in[0];      // [N,64]
    const int* ei = (const int*)d_in[1];         // [2,E] int32
    const float* pseudo = (const float*)d_in[2]; // [E,2]
    const float* skip = (const float*)d_in[3];   // [N,32]
    const float* W1 = (const float*)d_in[4];     // [9,64,32]
    const float* root1 = (const float*)d_in[5];  // [64,32]
    const float* b1 = (const float*)d_in[6];     // [32]
    const float* W2 = (const float*)d_in[7];     // [9,32,32]
    const float* root2 = (const float*)d_in[8];  // [32,32]
    const float* b2 = (const float*)d_in[9];     // [32]

    int Nn = in_sizes[0] / 64;
    int E = in_sizes[1] / 2;

    __half* Zh;
    float *acc1, *acc2;
    cudaGetSymbolAddress((void**)&Zh, g_Zh);
    cudaGetSymbolAddress((void**)&acc1, g_acc1);
    cudaGetSymbolAddress((void**)&acc2, g_acc2);

    const int BF4 = 4 * 40 * 32 * 8;  // 40960 B (KT=4)
    const int BF2 = 2 * 40 * 32 * 8;  // 20480 B (KT=2)

    int gb = (Nn + 127) / 128;  // 8 warps/block, 16 nodes/warp
    int eb = (E + 31) / 32;     // 4 edges/warp, 8 warps/block
    int nb4 = (Nn * 32 / 4 + 255) / 256;
    float* out = (float*)d_out;

    // ---- layer 1: x -> Zh, acc1(root) ; edge -> acc1
    node_hmma<4, 0><<<gb, 256, BF4>>>(x, nullptr, W1, root1, b1, Zh, acc1, Nn);
    edge_kernel<<<eb, 256>>>(Zh, ei, pseudo, acc1, E);

    // ---- layer 2: [relu(acc1)||skip] -> Zh, acc2(root) ; edge -> acc2
    node_hmma<4, 1><<<gb, 256, BF4>>>(acc1, skip, W1, root1, b1, Zh, acc2, Nn);
    edge_kernel<<<eb, 256>>>(Zh, ei, pseudo, acc2, E);

    // ---- layer 3: relu(acc2) -> Zh, out(root) ; edge -> out ; relu
    node_hmma<2, 2><<<gb, 256, BF2>>>(acc2, nullptr, W2, root2, b2, Zh, out, Nn);
    edge_kernel<<<eb, 256>>>(Zh, ei, pseudo, out, E);
    relu4_kernel<<<nb4, 256>>>((float4*)out, Nn * 32 / 4);
}

// round 16
// speedup vs baseline: 1.9756x; 1.0625x over previous
#include <cuda_runtime.h>
#include <cuda_fp16.h>

// ---------------------------------------------------------------------------
// MeshUpConv via node-domain weight transform, tensor-core node GEMM:
//   Z[n, k*32+o] = (X @ W[k])[n,o]  (HMMA m16n8k16, fp16 in / fp32 accum,
//   Z stored fp16); slot 9 = root -> acc (+bias, fp32).
//   edge: acc[dst, o] += sum_k B[e,k] * Z[src, k*32+o]
//   Edge contraction separable: inner k0-sum in HFMA2 (fp16), outer q1 in fp32.
// Bfrag tables precomputed once to global; node prologue = vectorized copy.
// edge_index arrives as int32 (JAX x64 disabled).
// ---------------------------------------------------------------------------

#define NMAX 50000
#define EMAX 400000

__device__ __half g_Zh[NMAX * 288];   // 28.8 MB
__device__ float g_acc1[NMAX * 32];
__device__ float g_acc2[NMAX * 32];
__device__ unsigned long long g_Bf1[4 * 40 * 32];  // KT=4 fragment table
__device__ unsigned long long g_Bf2[2 * 40 * 32];  // KT=2 fragment table

__device__ __forceinline__ void red_add_v4(float* addr, float a, float b,
                                           float c, float d) {
    asm volatile("red.global.add.v4.f32 [%0], {%1,%2,%3,%4};"
                 :: "l"(addr), "f"(a), "f"(b), "f"(c), "f"(d)
                 : "memory");
}

__device__ __forceinline__ unsigned h2u(float a, float b) {
    __half2 h = __floats2half2_rn(a, b);
    return *reinterpret_cast<unsigned*>(&h);
}

__device__ __forceinline__ void mma16816(float& c0, float& c1, float& c2,
                                         float& c3, unsigned a0, unsigned a1,
                                         unsigned a2, unsigned a3, unsigned b0,
                                         unsigned b1) {
    asm volatile(
        "mma.sync.aligned.m16n8k16.row.col.f32.f16.f16.f32 "
        "{%0,%1,%2,%3}, {%4,%5,%6,%7}, {%8,%9}, {%0,%1,%2,%3};"
        : "+f"(c0), "+f"(c1), "+f"(c2), "+f"(c3)
        : "r"(a0), "r"(a1), "r"(a2), "r"(a3), "r"(b0), "r"(b1));
}

// ---- one-time Bfrag table build (mma col-major k16 x n8 lane layout) -------
__global__ void build_bfrag(const float* __restrict__ W,
                            const float* __restrict__ root,
                            unsigned long long* __restrict__ out, int KT) {
    int CIN = KT * 16;
    int total = KT * 40 * 32;
    for (int i = blockIdx.x * blockDim.x + threadIdx.x; i < total;
         i += gridDim.x * blockDim.x) {
        int lane = i & 31;
        int nt = (i >> 5) % 40;
        int kt = i / (40 * 32);
        int g = lane >> 2, t = lane & 3;
        int n = nt * 8 + g;
        int slot = n >> 5, o = n & 31;
        int kbase = kt * 16 + t * 2;
        const float* src = (slot < 9) ? (W + slot * CIN * 32) : root;
        float w0 = src[(kbase + 0) * 32 + o];
        float w1 = src[(kbase + 1) * 32 + o];
        float w8 = src[(kbase + 8) * 32 + o];
        float w9 = src[(kbase + 9) * 32 + o];
        out[i] = (unsigned long long)h2u(w0, w1) |
                 ((unsigned long long)h2u(w8, w9) << 32);
    }
}

// ---- HMMA node GEMM: one m16-node tile per warp, 40 n8-tiles (320 cols) ----
// KT = k16 chunks (4 for CIN=64, 2 for CIN=32).
// MODE 0: X plain; MODE 1: [relu(A)||S]; MODE 2: relu(A).
template <int KT, int MODE>
__global__ void __launch_bounds__(256) node_hmma(
    const float* __restrict__ Xa, const float* __restrict__ Xb,
    const unsigned long long* __restrict__ BfG,
    const float* __restrict__ bias, __half* __restrict__ Zh,
    float* __restrict__ acc, int Nn) {
    extern __shared__ unsigned long long Bfrag[];  // [KT][40][32]
    __shared__ float bsm[32];

    // vectorized copy of the precomputed fragment table
    {
        uint4* dstv = reinterpret_cast<uint4*>(Bfrag);
        const uint4* srcv = reinterpret_cast<const uint4*>(BfG);
        const int TOT2 = KT * 40 * 16;  // u128 count
        for (int i = threadIdx.x; i < TOT2; i += 256) dstv[i] = __ldg(srcv + i);
    }
    if (threadIdx.x < 32) bsm[threadIdx.x] = bias[threadIdx.x];
    __syncthreads();

    const int CIN = KT * 16;
    int w = blockIdx.x * 8 + (threadIdx.x >> 5);
    int lane = threadIdx.x & 31;
    int n0 = w * 16;
    if (n0 >= Nn) return;
    int g = lane >> 2, t = lane & 3;
    int r1 = n0 + g, r2 = n0 + g + 8;
    int r1c = min(r1, Nn - 1), r2c = min(r2, Nn - 1);
    bool v1 = (r1 < Nn), v2 = (r2 < Nn);

    unsigned a[KT][4];
    if (MODE == 0) {
        const float2* x1 = reinterpret_cast<const float2*>(Xa + (long long)r1c * CIN);
        const float2* x2 = reinterpret_cast<const float2*>(Xa + (long long)r2c * CIN);
#pragma unroll
        for (int kc = 0; kc < KT; kc++) {
            float2 p;
            p = __ldg(x1 + kc * 8 + t);     a[kc][0] = h2u(p.x, p.y);
            p = __ldg(x2 + kc * 8 + t);     a[kc][1] = h2u(p.x, p.y);
            p = __ldg(x1 + kc * 8 + t + 4); a[kc][2] = h2u(p.x, p.y);
            p = __ldg(x2 + kc * 8 + t + 4); a[kc][3] = h2u(p.x, p.y);
        }
    } else if (MODE == 1) {
        const float2* x1 = reinterpret_cast<const float2*>(Xa + (long long)r1c * 32);
        const float2* x2 = reinterpret_cast<const float2*>(Xa + (long long)r2c * 32);
        const float2* s1 = reinterpret_cast<const float2*>(Xb + (long long)r1c * 32);
        const float2* s2 = reinterpret_cast<const float2*>(Xb + (long long)r2c * 32);
#pragma unroll
        for (int kc = 0; kc < 2; kc++) {
            float2 p;
            p = __ldg(x1 + kc * 8 + t);
            a[kc][0] = h2u(fmaxf(p.x, 0.f), fmaxf(p.y, 0.f));
            p = __ldg(x2 + kc * 8 + t);
            a[kc][1] = h2u(fmaxf(p.x, 0.f), fmaxf(p.y, 0.f));
            p = __ldg(x1 + kc * 8 + t + 4);
            a[kc][2] = h2u(fmaxf(p.x, 0.f), fmaxf(p.y, 0.f));
            p = __ldg(x2 + kc * 8 + t + 4);
            a[kc][3] = h2u(fmaxf(p.x, 0.f), fmaxf(p.y, 0.f));
            p = __ldg(s1 + kc * 8 + t);     a[kc + 2][0] = h2u(p.x, p.y);
            p = __ldg(s2 + kc * 8 + t);     a[kc + 2][1] = h2u(p.x, p.y);
            p = __ldg(s1 + kc * 8 + t + 4); a[kc + 2][2] = h2u(p.x, p.y);
            p = __ldg(s2 + kc * 8 + t + 4); a[kc + 2][3] = h2u(p.x, p.y);
        }
    } else {
        const float2* x1 = reinterpret_cast<const float2*>(Xa + (long long)r1c * 32);
        const float2* x2 = reinterpret_cast<const float2*>(Xa + (long long)r2c * 32);
#pragma unroll
        for (int kc = 0; kc < KT; kc++) {
            float2 p;
            p = __ldg(x1 + kc * 8 + t);
            a[kc][0] = h2u(fmaxf(p.x, 0.f), fmaxf(p.y, 0.f));
            p = __ldg(x2 + kc * 8 + t);
            a[kc][1] = h2u(fmaxf(p.x, 0.f), fmaxf(p.y, 0.f));
            p = __ldg(x1 + kc * 8 + t + 4);
            a[kc][2] = h2u(fmaxf(p.x, 0.f), fmaxf(p.y, 0.f));
            p = __ldg(x2 + kc * 8 + t + 4);
            a[kc][3] = h2u(fmaxf(p.x, 0.f), fmaxf(p.y, 0.f));
        }
    }

#pragma unroll
    for (int nt = 0; nt < 40; nt++) {
        float c0 = 0.f, c1 = 0.f, c2 = 0.f, c3 = 0.f;
#pragma unroll
        for (int kt = 0; kt < KT; kt++) {
            unsigned long long bb = Bfrag[(kt * 40 + nt) * 32 + lane];
            mma16816(c0, c1, c2, c3, a[kt][0], a[kt][1], a[kt][2], a[kt][3],
                     (unsigned)bb, (unsigned)(bb >> 32));
        }
        if (nt < 36) {  // slots 0-8 -> Zh fp16
            int col = (nt >> 2) * 32 + (nt & 3) * 8 + t * 2;
            if (v1)
                *reinterpret_cast<__half2*>(&Zh[(long long)r1 * 288 + col]) =
                    __floats2half2_rn(c0, c1);
            if (v2)
                *reinterpret_cast<__half2*>(&Zh[(long long)r2 * 288 + col]) =
                    __floats2half2_rn(c2, c3);
        } else {  // slot 9 = root -> acc fp32 + bias
            int col = (nt - 36) * 8 + t * 2;
            if (v1) {
                float2 f = make_float2(c0 + bsm[col], c1 + bsm[col + 1]);
                *reinterpret_cast<float2*>(&acc[(long long)r1 * 32 + col]) = f;
            }
            if (v2) {
                float2 f = make_float2(c2 + bsm[col], c3 + bsm[col + 1]);
                *reinterpret_cast<float2*>(&acc[(long long)r2 * 32 + col]) = f;
            }
        }
    }
}

// ---- edge phase: 8 lanes/edge, separable contraction ------------------------
// inner k0-sum in HFMA2 (3 fp16-rounded ops), outer q1 combine in fp32.
__global__ void __launch_bounds__(256) edge_kernel(
    const __half* __restrict__ Zh, const int* __restrict__ ei,
    const float* __restrict__ pseudo, float* __restrict__ acc, int E) {
    int warp = (blockIdx.x * 256 + threadIdx.x) >> 5;
    int lane = threadIdx.x & 31;
    int sub = lane >> 3;   // edge within warp (0..3)
    int li = lane & 7;     // half4-channel group (0..7)
    int e = warp * 4 + sub;
    if (e >= E) return;

    int s = __ldg(ei + e);
    int d = __ldg(ei + E + e);
    float2 ps = __ldg(reinterpret_cast<const float2*>(pseudo) + e);
    float t0 = ps.x, t1 = ps.y;

    float q1f[3];
    __half2 hq0[3];
    hq0[0] = __float2half2_rn(0.5f * (1.f - t0) * (1.f - t0));
    hq0[1] = __float2half2_rn(-t0 * t0 + t0 + 0.5f);
    hq0[2] = __float2half2_rn(0.5f * t0 * t0);
    q1f[0] = 0.5f * (1.f - t1) * (1.f - t1);
    q1f[1] = -t1 * t1 + t1 + 0.5f;
    q1f[2] = 0.5f * t1 * t1;

    const uint2* zs =
        reinterpret_cast<const uint2*>(Zh + (long long)s * 288) + li;
    float ax = 0.f, ay = 0.f, az = 0.f, aw = 0.f;
#pragma unroll
    for (int k1 = 0; k1 < 3; k1++) {
        uint2 z0 = __ldg(zs + (k1 * 3 + 0) * 8);
        uint2 z1 = __ldg(zs + (k1 * 3 + 1) * 8);
        uint2 z2 = __ldg(zs + (k1 * 3 + 2) * 8);
        __half2 h0 = __hmul2(hq0[0], *reinterpret_cast<__half2*>(&z0.x));
        __half2 h1 = __hmul2(hq0[0], *reinterpret_cast<__half2*>(&z0.y));
        h0 = __hfma2(hq0[1], *reinterpret_cast<__half2*>(&z1.x), h0);
        h1 = __hfma2(hq0[1], *reinterpret_cast<__half2*>(&z1.y), h1);
        h0 = __hfma2(hq0[2], *reinterpret_cast<__half2*>(&z2.x), h0);
        h1 = __hfma2(hq0[2], *reinterpret_cast<__half2*>(&z2.y), h1);
        float2 f0 = __half22float2(h0);
        float2 f1 = __half22float2(h1);
        ax = fmaf(q1f[k1], f0.x, ax);
        ay = fmaf(q1f[k1], f0.y, ay);
        az = fmaf(q1f[k1], f1.x, az);
        aw = fmaf(q1f[k1], f1.y, aw);
    }

    red_add_v4(acc + (long long)d * 32 + li * 4, ax, ay, az, aw);
}

__global__ void relu4_kernel(float4* __restrict__ a, int total4) {
    int i = blockIdx.x * blockDim.x + threadIdx.x;
    if (i < total4) {
        float4 v = a[i];
        v.x = fmaxf(v.x, 0.f); v.y = fmaxf(v.y, 0.f);
        v.z = fmaxf(v.z, 0.f); v.w = fmaxf(v.w, 0.f);
        a[i] = v;
    }
}

// ---------------------------------------------------------------------------
extern "C" void kernel_launch(void* const* d_in, const int* in_sizes, int n_in,
                              void* d_out, int out_size) {
    const float* x = (const float*)d_in[0];      // [N,64]
    const int* ei = (const int*)d_in[1];         // [2,E] int32
    const float* pseudo = (const float*)d_in[2]; // [E,2]
    const float* skip = (const float*)d_in[3];   // [N,32]
    const float* W1 = (const float*)d_in[4];     // [9,64,32]
    const float* root1 = (const float*)d_in[5];  // [64,32]
    const float* b1 = (const float*)d_in[6];     // [32]
    const float* W2 = (const float*)d_in[7];     // [9,32,32]
    const float* root2 = (const float*)d_in[8];  // [32,32]
    const float* b2 = (const float*)d_in[9];     // [32]

    int Nn = in_sizes[0] / 64;
    int E = in_sizes[1] / 2;

    __half* Zh;
    float *acc1, *acc2;
    unsigned long long *Bf1, *Bf2;
    cudaGetSymbolAddress((void**)&Zh, g_Zh);
    cudaGetSymbolAddress((void**)&acc1, g_acc1);
    cudaGetSymbolAddress((void**)&acc2, g_acc2);
    cudaGetSymbolAddress((void**)&Bf1, g_Bf1);
    cudaGetSymbolAddress((void**)&Bf2, g_Bf2);

    const int BF4 = 4 * 40 * 32 * 8;  // 40960 B (KT=4)
    const int BF2 = 2 * 40 * 32 * 8;  // 20480 B (KT=2)

    int gb = (Nn + 127) / 128;  // 8 warps/block, 16 nodes/warp
    int eb = (E + 31) / 32;     // 4 edges/warp, 8 warps/block
    int nb4 = (Nn * 32 / 4 + 255) / 256;
    float* out = (float*)d_out;

    // ---- one-time fragment tables
    build_bfrag<<<20, 256>>>(W1, root1, Bf1, 4);
    build_bfrag<<<10, 256>>>(W2, root2, Bf2, 2);

    // ---- layer 1: x -> Zh, acc1(root) ; edge -> acc1
    node_hmma<4, 0><<<gb, 256, BF4>>>(x, nullptr, Bf1, b1, Zh, acc1, Nn);
    edge_kernel<<<eb, 256>>>(Zh, ei, pseudo, acc1, E);

    // ---- layer 2: [relu(acc1)||skip] -> Zh, acc2(root) ; edge -> acc2
    node_hmma<4, 1><<<gb, 256, BF4>>>(acc1, skip, Bf1, b1, Zh, acc2, Nn);
    edge_kernel<<<eb, 256>>>(Zh, ei, pseudo, acc2, E);

    // ---- layer 3: relu(acc2) -> Zh, out(root) ; edge -> out ; relu
    node_hmma<2, 2><<<gb, 256, BF2>>>(acc2, nullptr, Bf2, b2, Zh, out, Nn);
    edge_kernel<<<eb, 256>>>(Zh, ei, pseudo, out, E);
    relu4_kernel<<<nb4, 256>>>((float4*)out, Nn * 32 / 4);
}